// round 4
// baseline (speedup 1.0000x reference)
#include <cuda_runtime.h>
#include <cstdint>

#define BB 256
#define TT 1024
#define WW 512
#define UU 512
#define PP 16
#define TP (TT - PP + 1)
#define MTOT (BB * TP)

__device__ float g_syn[(size_t)BB * TP * WW];
__device__ float g_state[2][BB * UU];
__device__ unsigned g_flags[8][16 * 32];   // [batch-tile][u-tile], padded 128B

typedef unsigned long long u64;
__device__ __forceinline__ u64 pack2(float lo, float hi) {
    u64 r; asm("mov.b64 %0, {%1, %2};" : "=l"(r) : "f"(lo), "f"(hi)); return r;
}
__device__ __forceinline__ void unpack2(u64 v, float& lo, float& hi) {
    asm("mov.b64 {%0, %1}, %2;" : "=f"(lo), "=f"(hi) : "l"(v));
}
__device__ __forceinline__ void ffma2(u64& c, u64 a, u64 b) {
    asm("fma.rn.f32x2 %0, %1, %2, %0;" : "+l"(c) : "l"(a), "l"(b));
}
__device__ __forceinline__ void fadd2(u64& a, u64 b) {
    asm("add.rn.f32x2 %0, %0, %1;" : "+l"(a) : "l"(b));
}
__device__ __forceinline__ unsigned ld_acq(const unsigned* p) {
    unsigned v;
    asm volatile("ld.global.acquire.gpu.u32 %0, [%1];" : "=r"(v) : "l"(p) : "memory");
    return v;
}
__device__ __forceinline__ void st_rel(unsigned* p, unsigned v) {
    asm volatile("st.global.release.gpu.u32 [%0], %1;" :: "l"(p), "r"(v) : "memory");
}
__device__ __forceinline__ float4 ldcg_f4(const float4* p) {
    float4 v;
    asm volatile("ld.global.cg.v4.f32 {%0,%1,%2,%3}, [%4];"
                 : "=f"(v.x), "=f"(v.y), "=f"(v.z), "=f"(v.w) : "l"(p) : "memory");
    return v;
}
__device__ __forceinline__ void stcg_f4(float4* p, float4 v) {
    asm volatile("st.global.cg.v4.f32 [%0], {%1,%2,%3,%4};"
                 :: "l"(p), "f"(v.x), "f"(v.y), "f"(v.z), "f"(v.w) : "memory");
}

// ---- init ----
__global__ void init_kernel() {
    const int i = blockIdx.x * 256 + threadIdx.x;
    if (i < BB * UU) g_state[0][i] = 0.0f;
    if (i < 8 * 16 * 32) ((unsigned*)g_flags)[i] = 0u;
}

// ---- 1) depthwise temporal conv ----
__global__ void conv_kernel(const float* __restrict__ x, const float* __restrict__ pw,
                            const float* __restrict__ pb) {
    const int t = blockIdx.x, b = blockIdx.y, w4 = threadIdx.x;
    const float bias = pb[0];
    float4 acc = make_float4(bias, bias, bias, bias);
    const float4* xp = reinterpret_cast<const float4*>(x) + ((size_t)b * TT + t) * (WW / 4) + w4;
#pragma unroll
    for (int k = 0; k < PP; k++) {
        const float c = __ldg(&pw[k]);
        const float4 xv = xp[(size_t)k * (WW / 4)];
        acc.x += c * xv.x; acc.y += c * xv.y; acc.z += c * xv.z; acc.w += c * xv.w;
    }
    reinterpret_cast<float4*>(g_syn)[((size_t)b * TP + t) * (WW / 4) + w4] = acc;
}

// ---- 2) pre = syn @ K + bias ----
#define BM 128
#define BN 128
#define BK 16
__global__ __launch_bounds__(256) void gemm_kernel(const float* __restrict__ Bw,
                                                   const float* __restrict__ bias,
                                                   float* __restrict__ C) {
    __shared__ __align__(16) float As[BK][BM];
    __shared__ __align__(16) float Bs[BK][BN];
    const int tid = threadIdx.x, tn = tid & 15, tm = tid >> 4;
    const size_t m0 = (size_t)blockIdx.y * BM;
    const int n0 = blockIdx.x * BN;

    u64 acc[8][4];
#pragma unroll
    for (int i = 0; i < 8; i++)
#pragma unroll
        for (int q = 0; q < 4; q++) acc[i][q] = 0ULL;

    for (int k0 = 0; k0 < WW; k0 += BK) {
#pragma unroll
        for (int r = 0; r < 2; r++) {
            const int f = tid + (r << 8), row = f >> 2, kk = (f & 3) << 2;
            const float4 v = *(const float4*)&g_syn[(m0 + row) * WW + k0 + kk];
            As[kk][row] = v.x; As[kk + 1][row] = v.y; As[kk + 2][row] = v.z; As[kk + 3][row] = v.w;
        }
#pragma unroll
        for (int r = 0; r < 2; r++) {
            const int f = tid + (r << 8), row = f >> 5, c = (f & 31) << 2;
            *(float4*)&Bs[row][c] = *(const float4*)&Bw[(size_t)(k0 + row) * UU + n0 + c];
        }
        __syncthreads();
#pragma unroll
        for (int k = 0; k < BK; k++) {
            const float4 a0 = *(const float4*)&As[k][tm << 3];
            const float4 a1 = *(const float4*)&As[k][(tm << 3) + 4];
            const double2* bp = (const double2*)&Bs[k][tn << 3];
            const double2 bA = bp[0], bB = bp[1];
            const u64 b0 = __double_as_longlong(bA.x), b1 = __double_as_longlong(bA.y);
            const u64 b2 = __double_as_longlong(bB.x), b3 = __double_as_longlong(bB.y);
            const float av[8] = {a0.x, a0.y, a0.z, a0.w, a1.x, a1.y, a1.z, a1.w};
#pragma unroll
            for (int i = 0; i < 8; i++) {
                const u64 ap = pack2(av[i], av[i]);
                ffma2(acc[i][0], ap, b0); ffma2(acc[i][1], ap, b1);
                ffma2(acc[i][2], ap, b2); ffma2(acc[i][3], ap, b3);
            }
        }
        __syncthreads();
    }
    float bb[8];
#pragma unroll
    for (int j = 0; j < 8; j++) bb[j] = bias[n0 + (tn << 3) + j];
#pragma unroll
    for (int i = 0; i < 8; i++) {
        float r[8];
#pragma unroll
        for (int q = 0; q < 4; q++) unpack2(acc[i][q], r[2 * q], r[2 * q + 1]);
#pragma unroll
        for (int j = 0; j < 8; j++) r[j] += bb[j];
        const size_t off = (m0 + (tm << 3) + i) * UU + n0 + (tn << 3);
        *(float4*)&C[off] = make_float4(r[0], r[1], r[2], r[3]);
        *(float4*)&C[off + 4] = make_float4(r[4], r[5], r[6], r[7]);
    }
}

// ---- 3) persistent recurrence: 128 CTAs = 8 batch-tiles x 16 u-tiles ----
#define SS_STRIDE 516
#define RNN_SMEM ((512 * 32 + 32 * SS_STRIDE) * 4)

__global__ __launch_bounds__(256, 1) void rnn_persistent_kernel(
        const float* __restrict__ Rm, float* __restrict__ C) {
    extern __shared__ __align__(16) float smem[];
    float* Rs = smem;                 // [512][32] resident whole sequence
    float* Ss = smem + 512 * 32;      // [32][516] per-step state tile
    u64*   buf = (u64*)Ss;            // reduction buffer aliases Ss

    const int tid  = threadIdx.x;
    const int lane = tid & 31, wid = tid >> 5;
    const int ut = blockIdx.x;        // 0..15
    const int bt = blockIdx.y;        // 0..7
    const int n0 = ut << 5;
    const int b0 = bt << 5;

    for (int f = tid; f < 512 * 8; f += 256) {
        const int k = f >> 3, c = (f & 7) << 2;
        *(float4*)&Rs[k * 32 + c] = *(const float4*)&Rm[(size_t)k * UU + n0 + c];
    }

    const int bq = lane >> 3;
    const int uq = lane & 7;
    const int kbase = wid << 6;

    const int s0 = tid * 2;
    const int lane_src = s0 >> 4;
    const int e_i = (s0 & 15) >> 1;
    const int e_b = (e_i << 2) + (lane_src >> 3);
    const int e_u = (lane_src & 7) << 2;

    for (int t = 0; t < TP; t++) {
        const int p = t & 1;
        if (t > 0 && tid < 16) {
            const unsigned* fp = &g_flags[bt][tid * 32];
            while (ld_acq(fp) < (unsigned)t) {}
        }
        __syncthreads();

        for (int f = tid; f < 32 * 128; f += 256) {
            const int b = f >> 7, c = (f & 127) << 2;
            const float4 v = ldcg_f4((const float4*)&g_state[p][(size_t)(b0 + b) * UU + c]);
            *(float4*)&Ss[b * SS_STRIDE + c] = v;
        }
        __syncthreads();

        u64 acc[8][2];
#pragma unroll
        for (int i = 0; i < 8; i++) { acc[i][0] = 0ULL; acc[i][1] = 0ULL; }

#pragma unroll 2
        for (int kc = 0; kc < 16; kc++) {
            const int k = kbase + (kc << 2);
            float4 sv[8];
#pragma unroll
            for (int i = 0; i < 8; i++)
                sv[i] = *(const float4*)&Ss[((i << 2) + bq) * SS_STRIDE + k];
#pragma unroll
            for (int kk = 0; kk < 4; kk++) {
                const double2 rd = *(const double2*)&Rs[(k + kk) * 32 + (uq << 2)];
                const u64 r01 = __double_as_longlong(rd.x);
                const u64 r23 = __double_as_longlong(rd.y);
#pragma unroll
                for (int i = 0; i < 8; i++) {
                    const float s = (kk == 0) ? sv[i].x : (kk == 1) ? sv[i].y
                                  : (kk == 2) ? sv[i].z : sv[i].w;
                    const u64 sp = pack2(s, s);
                    ffma2(acc[i][0], sp, r01);
                    ffma2(acc[i][1], sp, r23);
                }
            }
        }
        __syncthreads();

#pragma unroll
        for (int i = 0; i < 8; i++) {
            buf[(wid << 9) + (lane << 4) + (i << 1)]     = acc[i][0];
            buf[(wid << 9) + (lane << 4) + (i << 1) + 1] = acc[i][1];
        }
        __syncthreads();

        u64 a0 = buf[s0], a1 = buf[s0 + 1];
#pragma unroll
        for (int w = 1; w < 8; w++) {
            fadd2(a0, buf[(w << 9) + s0]);
            fadd2(a1, buf[(w << 9) + s0 + 1]);
        }
        float d0, d1, d2, d3;
        unpack2(a0, d0, d1); unpack2(a1, d2, d3);

        const int bglob = b0 + e_b;
        const size_t crow = ((size_t)bglob * TP + t) * UU + n0 + e_u;
        const float4 pre = *(const float4*)&C[crow];
        const float o[4] = {pre.x + d0, pre.y + d1, pre.z + d2, pre.w + d3};
        float nn[4], st[4];
#pragma unroll
        for (int j = 0; j < 4; j++) {
            const float n = 1.0f / (1.0f + expf(-3.0f * o[j]));   // precise expf
            nn[j] = n;
            st[j] = o[j] / (1.0f + expf(2.0f * n - 1.0f));
        }
        *(float4*)&C[crow] = make_float4(nn[0], nn[1], nn[2], nn[3]);
        stcg_f4((float4*)&g_state[p ^ 1][(size_t)bglob * UU + n0 + e_u],
                make_float4(st[0], st[1], st[2], st[3]));

        __threadfence();
        __syncthreads();
        if (tid == 0) st_rel(&g_flags[bt][ut * 32], (unsigned)(t + 1));
    }
}

extern "C" void kernel_launch(void* const* d_in, const int* in_sizes, int n_in,
                              void* d_out, int out_size) {
    const float* x    = (const float*)d_in[0];
    const float* pw   = (const float*)d_in[1];
    const float* pb   = (const float*)d_in[2];
    const float* Kw   = (const float*)d_in[3];
    const float* Rm   = (const float*)d_in[4];
    const float* bias = (const float*)d_in[5];
    float* out = (float*)d_out;

    cudaFuncSetAttribute(rnn_persistent_kernel,
                         cudaFuncAttributeMaxDynamicSharedMemorySize, RNN_SMEM);

    init_kernel<<<(BB * UU) / 256, 256>>>();
    conv_kernel<<<dim3(TP, BB), 128>>>(x, pw, pb);
    gemm_kernel<<<dim3(UU / BN, MTOT / BM), 256>>>(Kw, bias, out);
    rnn_persistent_kernel<<<dim3(16, 8), 256, RNN_SMEM>>>(Rm, out);
}

// round 6
// speedup vs baseline: 1.1810x; 1.1810x over previous
#include <cuda_runtime.h>
#include <cuda_bf16.h>
#include <cstdint>

#define BB 256
#define TT 1024
#define WW 512
#define UU 512
#define PP 16
#define TP (TT - PP + 1)
#define MTOT (BB * TP)

__device__ __align__(16) __nv_bfloat16 g_Ah[(size_t)MTOT * WW];
__device__ __align__(16) __nv_bfloat16 g_Al[(size_t)MTOT * WW];
__device__ __align__(16) __nv_bfloat16 g_Bh[WW * UU];   // K^T hi [n][k]
__device__ __align__(16) __nv_bfloat16 g_Bl[WW * UU];   // K^T lo [n][k]
__device__ float g_state[2][BB * UU];
__device__ unsigned g_flags[8][16 * 32];

typedef unsigned long long u64;
__device__ __forceinline__ u64 pack2(float lo, float hi) {
    u64 r; asm("mov.b64 %0, {%1, %2};" : "=l"(r) : "f"(lo), "f"(hi)); return r;
}
__device__ __forceinline__ void unpack2(u64 v, float& lo, float& hi) {
    asm("mov.b64 {%0, %1}, %2;" : "=f"(lo), "=f"(hi) : "l"(v));
}
__device__ __forceinline__ void ffma2(u64& c, u64 a, u64 b) {
    asm("fma.rn.f32x2 %0, %1, %2, %0;" : "+l"(c) : "l"(a), "l"(b));
}
__device__ __forceinline__ void fadd2(u64& a, u64 b) {
    asm("add.rn.f32x2 %0, %0, %1;" : "+l"(a) : "l"(b));
}
__device__ __forceinline__ unsigned ld_acq(const unsigned* p) {
    unsigned v;
    asm volatile("ld.global.acquire.gpu.u32 %0, [%1];" : "=r"(v) : "l"(p) : "memory");
    return v;
}
__device__ __forceinline__ void st_rel(unsigned* p, unsigned v) {
    asm volatile("st.global.release.gpu.u32 [%0], %1;" :: "l"(p), "r"(v) : "memory");
}
__device__ __forceinline__ float4 ldcg_f4(const float4* p) {
    float4 v;
    asm volatile("ld.global.cg.v4.f32 {%0,%1,%2,%3}, [%4];"
                 : "=f"(v.x), "=f"(v.y), "=f"(v.z), "=f"(v.w) : "l"(p) : "memory");
    return v;
}
__device__ __forceinline__ void stcg_f4(float4* p, float4 v) {
    asm volatile("st.global.cg.v4.f32 [%0], {%1,%2,%3,%4};"
                 :: "l"(p), "f"(v.x), "f"(v.y), "f"(v.z), "f"(v.w) : "memory");
}
__device__ __forceinline__ uint32_t smem_u32(const void* p) {
    uint32_t a;
    asm("{ .reg .u64 t; cvta.to.shared.u64 t, %1; cvt.u32.u64 %0, t; }" : "=r"(a) : "l"(p));
    return a;
}
__device__ __forceinline__ void cpa16(uint32_t s, const void* g) {
    asm volatile("cp.async.cg.shared.global [%0], [%1], 16;" :: "r"(s), "l"(g) : "memory");
}
#define SWZ(x) ((x) ^ (((x) >> 3) & 0x70))
#define LDSM4(r0, r1, r2, r3, a) \
    asm volatile("ldmatrix.sync.aligned.m8n8.x4.shared.b16 {%0,%1,%2,%3}, [%4];" \
                 : "=r"(r0), "=r"(r1), "=r"(r2), "=r"(r3) : "r"(a))
__device__ __forceinline__ void mma_bf16(float* c, const uint32_t* a, const uint32_t* b) {
    asm volatile(
        "mma.sync.aligned.m16n8k16.row.col.f32.bf16.bf16.f32 "
        "{%0,%1,%2,%3}, {%4,%5,%6,%7}, {%8,%9}, {%0,%1,%2,%3};"
        : "+f"(c[0]), "+f"(c[1]), "+f"(c[2]), "+f"(c[3])
        : "r"(a[0]), "r"(a[1]), "r"(a[2]), "r"(a[3]), "r"(b[0]), "r"(b[1]));
}

// ---- init ----
__global__ void init_kernel() {
    const int i = blockIdx.x * 256 + threadIdx.x;
    if (i < BB * UU) g_state[0][i] = 0.0f;
    if (i < 8 * 16 * 32) ((unsigned*)g_flags)[i] = 0u;
}

// ---- prep: K^T hi/lo bf16 split ----
__global__ void prep_b_kernel(const float* __restrict__ Kw) {
    const int i = blockIdx.x * 256 + threadIdx.x;
    const int n = i >> 9, k = i & 511;
    const float v = __ldg(&Kw[(size_t)k * UU + n]);
    const __nv_bfloat16 h = __float2bfloat16(v);
    g_Bh[i] = h;
    g_Bl[i] = __float2bfloat16(v - __bfloat162float(h));
}

// ---- 1) conv, emits syn as bf16 hi/lo ----
__global__ void conv_kernel(const float* __restrict__ x, const float* __restrict__ pw,
                            const float* __restrict__ pb) {
    const int t = blockIdx.x, b = blockIdx.y, w4 = threadIdx.x;
    const float bias = pb[0];
    float4 acc = make_float4(bias, bias, bias, bias);
    const float4* xp = reinterpret_cast<const float4*>(x) + ((size_t)b * TT + t) * (WW / 4) + w4;
#pragma unroll
    for (int k = 0; k < PP; k++) {
        const float c = __ldg(&pw[k]);
        const float4 xv = xp[(size_t)k * (WW / 4)];
        acc.x += c * xv.x; acc.y += c * xv.y; acc.z += c * xv.z; acc.w += c * xv.w;
    }
    const float vv[4] = {acc.x, acc.y, acc.z, acc.w};
    uint32_t hw[2] = {0, 0}, lw[2] = {0, 0};
#pragma unroll
    for (int j = 0; j < 4; j++) {
        const __nv_bfloat16 h = __float2bfloat16(vv[j]);
        const __nv_bfloat16 l = __float2bfloat16(vv[j] - __bfloat162float(h));
        hw[j >> 1] |= (uint32_t)__bfloat16_as_ushort(h) << ((j & 1) * 16);
        lw[j >> 1] |= (uint32_t)__bfloat16_as_ushort(l) << ((j & 1) * 16);
    }
    const size_t idx = ((size_t)b * TP + t) * WW + w4 * 4;
    *(uint2*)&g_Ah[idx] = make_uint2(hw[0], hw[1]);
    *(uint2*)&g_Al[idx] = make_uint2(lw[0], lw[1]);
}

// ---- 2) pre = syn @ K + bias, bf16x3 mma.sync ----
// CTA 128x128, BK=64, 8 warps (4M x 2N), warp tile 32x64, 2-stage cp.async.
#define GEMM_SMEM 131072
__global__ __launch_bounds__(256, 1) void gemm_mma_kernel(const float* __restrict__ bias,
                                                          float* __restrict__ C) {
    extern __shared__ __align__(1024) char smem[];
    const uint32_t sb = smem_u32(smem);
    const int tid = threadIdx.x, lane = tid & 31, wid = tid >> 5;
    const int warp_m = wid & 3, warp_n = wid >> 2;
    const size_t m0 = (size_t)blockIdx.y * 128;
    const int n0 = blockIdx.x * 128;

    float acc[2][8][4];
#pragma unroll
    for (int i = 0; i < 2; i++)
#pragma unroll
        for (int j = 0; j < 8; j++)
#pragma unroll
            for (int q = 0; q < 4; q++) acc[i][j][q] = 0.0f;

    const int lcol = tid & 7, lrow = tid >> 3;
    auto load_stage = [&](int st, int k0) {
        const uint32_t sst = sb + st * 65536;
#pragma unroll
        for (int buf = 0; buf < 4; buf++) {
            const __nv_bfloat16* src = (buf == 0) ? g_Ah : (buf == 1) ? g_Al
                                     : (buf == 2) ? g_Bh : g_Bl;
            const size_t rbase = (buf < 2) ? m0 : (size_t)n0;
            const uint32_t sbuf = sst + buf * 16384;
#pragma unroll
            for (int i = 0; i < 4; i++) {
                const int row = lrow + 32 * i;
                cpa16(sbuf + SWZ((uint32_t)(row * 128 + lcol * 16)),
                      src + (rbase + row) * 512 + k0 + lcol * 8);
            }
        }
    };

    load_stage(0, 0);
    asm volatile("cp.async.commit_group;" ::: "memory");

    const int rsel = lane >> 3, rlow = lane & 7;
    const int radd = (rsel & 1) << 3, cadd = rsel >> 1;

    for (int c = 0; c < 8; c++) {
        if (c < 7) {
            load_stage((c + 1) & 1, (c + 1) << 6);
            asm volatile("cp.async.commit_group;" ::: "memory");
            asm volatile("cp.async.wait_group 1;" ::: "memory");
        } else {
            asm volatile("cp.async.wait_group 0;" ::: "memory");
        }
        __syncthreads();

        const uint32_t ss = sb + (c & 1) * 65536;
#pragma unroll
        for (int ks = 0; ks < 4; ks++) {
            uint32_t a[2][2][4];
#pragma unroll
            for (int h = 0; h < 2; h++)
#pragma unroll
                for (int mf = 0; mf < 2; mf++) {
                    const int row = warp_m * 32 + mf * 16 + radd + rlow;
                    const int col = ks * 2 + cadd;
                    const uint32_t ad = ss + h * 16384 + SWZ((uint32_t)(row * 128 + col * 16));
                    LDSM4(a[h][mf][0], a[h][mf][1], a[h][mf][2], a[h][mf][3], ad);
                }
            uint32_t b[2][8][2];
#pragma unroll
            for (int h = 0; h < 2; h++)
#pragma unroll
                for (int pr = 0; pr < 4; pr++) {
                    const int row = warp_n * 64 + pr * 16 + radd + rlow;
                    const int col = ks * 2 + cadd;
                    const uint32_t ad = ss + 32768 + h * 16384 +
                                        SWZ((uint32_t)(row * 128 + col * 16));
                    uint32_t r0, r1, r2, r3;
                    LDSM4(r0, r1, r2, r3, ad);
                    b[h][pr * 2][0] = r0; b[h][pr * 2 + 1][0] = r1;
                    b[h][pr * 2][1] = r2; b[h][pr * 2 + 1][1] = r3;
                }
#pragma unroll
            for (int mf = 0; mf < 2; mf++)
#pragma unroll
                for (int nf = 0; nf < 8; nf++) {
                    mma_bf16(acc[mf][nf], a[0][mf], b[0][nf]);
                    mma_bf16(acc[mf][nf], a[0][mf], b[1][nf]);
                    mma_bf16(acc[mf][nf], a[1][mf], b[0][nf]);
                }
        }
        __syncthreads();
    }

#pragma unroll
    for (int mf = 0; mf < 2; mf++) {
        const int row = warp_m * 32 + mf * 16 + (lane >> 2);
        const size_t gr0 = (m0 + row) * 512;
        const size_t gr1 = (m0 + row + 8) * 512;
#pragma unroll
        for (int nf = 0; nf < 8; nf++) {
            const int col = n0 + warp_n * 64 + nf * 8 + (lane & 3) * 2;
            const float2 bv = *(const float2*)&bias[col];
            *(float2*)&C[gr0 + col] =
                make_float2(acc[mf][nf][0] + bv.x, acc[mf][nf][1] + bv.y);
            *(float2*)&C[gr1 + col] =
                make_float2(acc[mf][nf][2] + bv.x, acc[mf][nf][3] + bv.y);
        }
    }
}

// ---- 3) persistent recurrence (unchanged) ----
#define SS_STRIDE 516
#define RNN_SMEM ((512 * 32 + 32 * SS_STRIDE) * 4)

__global__ __launch_bounds__(256, 1) void rnn_persistent_kernel(
        const float* __restrict__ Rm, float* __restrict__ C) {
    extern __shared__ __align__(16) float fsmem[];
    float* Rs = fsmem;
    float* Ss = fsmem + 512 * 32;
    u64*   buf = (u64*)Ss;

    const int tid  = threadIdx.x;
    const int lane = tid & 31, wid = tid >> 5;
    const int ut = blockIdx.x;
    const int bt = blockIdx.y;
    const int n0 = ut << 5;
    const int b0 = bt << 5;

    for (int f = tid; f < 512 * 8; f += 256) {
        const int k = f >> 3, c = (f & 7) << 2;
        *(float4*)&Rs[k * 32 + c] = *(const float4*)&Rm[(size_t)k * UU + n0 + c];
    }

    const int bq = lane >> 3;
    const int uq = lane & 7;
    const int kbase = wid << 6;

    const int s0 = tid * 2;
    const int lane_src = s0 >> 4;
    const int e_i = (s0 & 15) >> 1;
    const int e_b = (e_i << 2) + (lane_src >> 3);
    const int e_u = (lane_src & 7) << 2;

    for (int t = 0; t < TP; t++) {
        const int p = t & 1;
        if (t > 0 && tid < 16) {
            const unsigned* fp = &g_flags[bt][tid * 32];
            while (ld_acq(fp) < (unsigned)t) {}
        }
        __syncthreads();

        for (int f = tid; f < 32 * 128; f += 256) {
            const int b = f >> 7, c = (f & 127) << 2;
            const float4 v = ldcg_f4((const float4*)&g_state[p][(size_t)(b0 + b) * UU + c]);
            *(float4*)&Ss[b * SS_STRIDE + c] = v;
        }
        __syncthreads();

        u64 acc[8][2];
#pragma unroll
        for (int i = 0; i < 8; i++) { acc[i][0] = 0ULL; acc[i][1] = 0ULL; }

#pragma unroll 2
        for (int kc = 0; kc < 16; kc++) {
            const int k = kbase + (kc << 2);
            float4 sv[8];
#pragma unroll
            for (int i = 0; i < 8; i++)
                sv[i] = *(const float4*)&Ss[((i << 2) + bq) * SS_STRIDE + k];
#pragma unroll
            for (int kk = 0; kk < 4; kk++) {
                const double2 rd = *(const double2*)&Rs[(k + kk) * 32 + (uq << 2)];
                const u64 r01 = __double_as_longlong(rd.x);
                const u64 r23 = __double_as_longlong(rd.y);
#pragma unroll
                for (int i = 0; i < 8; i++) {
                    const float s = (kk == 0) ? sv[i].x : (kk == 1) ? sv[i].y
                                  : (kk == 2) ? sv[i].z : sv[i].w;
                    const u64 sp = pack2(s, s);
                    ffma2(acc[i][0], sp, r01);
                    ffma2(acc[i][1], sp, r23);
                }
            }
        }
        __syncthreads();

#pragma unroll
        for (int i = 0; i < 8; i++) {
            buf[(wid << 9) + (lane << 4) + (i << 1)]     = acc[i][0];
            buf[(wid << 9) + (lane << 4) + (i << 1) + 1] = acc[i][1];
        }
        __syncthreads();

        u64 a0 = buf[s0], a1 = buf[s0 + 1];
#pragma unroll
        for (int w = 1; w < 8; w++) {
            fadd2(a0, buf[(w << 9) + s0]);
            fadd2(a1, buf[(w << 9) + s0 + 1]);
        }
        float d0, d1, d2, d3;
        unpack2(a0, d0, d1); unpack2(a1, d2, d3);

        const int bglob = b0 + e_b;
        const size_t crow = ((size_t)bglob * TP + t) * UU + n0 + e_u;
        const float4 pre = *(const float4*)&C[crow];
        const float o[4] = {pre.x + d0, pre.y + d1, pre.z + d2, pre.w + d3};
        float nn[4], st[4];
#pragma unroll
        for (int j = 0; j < 4; j++) {
            const float n = 1.0f / (1.0f + expf(-3.0f * o[j]));
            nn[j] = n;
            st[j] = o[j] / (1.0f + expf(2.0f * n - 1.0f));
        }
        *(float4*)&C[crow] = make_float4(nn[0], nn[1], nn[2], nn[3]);
        stcg_f4((float4*)&g_state[p ^ 1][(size_t)bglob * UU + n0 + e_u],
                make_float4(st[0], st[1], st[2], st[3]));

        __threadfence();
        __syncthreads();
        if (tid == 0) st_rel(&g_flags[bt][ut * 32], (unsigned)(t + 1));
    }
}

extern "C" void kernel_launch(void* const* d_in, const int* in_sizes, int n_in,
                              void* d_out, int out_size) {
    const float* x    = (const float*)d_in[0];
    const float* pw   = (const float*)d_in[1];
    const float* pb   = (const float*)d_in[2];
    const float* Kw   = (const float*)d_in[3];
    const float* Rm   = (const float*)d_in[4];
    const float* bias = (const float*)d_in[5];
    float* out = (float*)d_out;

    cudaFuncSetAttribute(rnn_persistent_kernel,
                         cudaFuncAttributeMaxDynamicSharedMemorySize, RNN_SMEM);
    cudaFuncSetAttribute(gemm_mma_kernel,
                         cudaFuncAttributeMaxDynamicSharedMemorySize, GEMM_SMEM);

    init_kernel<<<(BB * UU) / 256, 256>>>();
    prep_b_kernel<<<(WW * UU) / 256, 256>>>(Kw);
    conv_kernel<<<dim3(TP, BB), 128>>>(x, pw, pb);
    gemm_mma_kernel<<<dim3(UU / 128, MTOT / 128), 256, GEMM_SMEM>>>(bias, out);
    rnn_persistent_kernel<<<dim3(16, 8), 256, RNN_SMEM>>>(Rm, out);
}

// round 7
// speedup vs baseline: 1.7732x; 1.5014x over previous
#include <cuda_runtime.h>
#include <cuda_bf16.h>
#include <cstdint>

#define BB 256
#define TT 1024
#define WW 512
#define UU 512
#define PP 16
#define TP (TT - PP + 1)
#define MTOT (BB * TP)

__device__ __align__(16) __nv_bfloat16 g_Ah[(size_t)MTOT * WW];
__device__ __align__(16) __nv_bfloat16 g_Al[(size_t)MTOT * WW];
__device__ __align__(16) __nv_bfloat16 g_Bh[WW * UU];    // K^T hi [n][k]
__device__ __align__(16) __nv_bfloat16 g_Bl[WW * UU];    // K^T lo [n][k]
__device__ __align__(16) __nv_bfloat16 g_Rth[UU * UU];   // R^T hi [n][k]
__device__ __align__(16) __nv_bfloat16 g_Rtl[UU * UU];   // R^T lo [n][k]
__device__ __align__(16) __nv_bfloat16 g_sbf[2][2][BB * UU]; // [parity][hi/lo]
__device__ unsigned g_flags[8][16 * 32];

typedef unsigned long long u64;
__device__ __forceinline__ unsigned ld_acq(const unsigned* p) {
    unsigned v;
    asm volatile("ld.global.acquire.gpu.u32 %0, [%1];" : "=r"(v) : "l"(p) : "memory");
    return v;
}
__device__ __forceinline__ void st_rel(unsigned* p, unsigned v) {
    asm volatile("st.global.release.gpu.u32 [%0], %1;" :: "l"(p), "r"(v) : "memory");
}
__device__ __forceinline__ uint32_t smem_u32(const void* p) {
    uint32_t a;
    asm("{ .reg .u64 t; cvta.to.shared.u64 t, %1; cvt.u32.u64 %0, t; }" : "=r"(a) : "l"(p));
    return a;
}
__device__ __forceinline__ void cpa16(uint32_t s, const void* g) {
    asm volatile("cp.async.cg.shared.global [%0], [%1], 16;" :: "r"(s), "l"(g) : "memory");
}
#define SWZ(x) ((x) ^ (((x) >> 3) & 0x70))
#define LDSM4(r0, r1, r2, r3, a) \
    asm volatile("ldmatrix.sync.aligned.m8n8.x4.shared.b16 {%0,%1,%2,%3}, [%4];" \
                 : "=r"(r0), "=r"(r1), "=r"(r2), "=r"(r3) : "r"(a))
__device__ __forceinline__ void mma_bf16(float* c, const uint32_t* a, const uint32_t* b) {
    asm volatile(
        "mma.sync.aligned.m16n8k16.row.col.f32.bf16.bf16.f32 "
        "{%0,%1,%2,%3}, {%4,%5,%6,%7}, {%8,%9}, {%0,%1,%2,%3};"
        : "+f"(c[0]), "+f"(c[1]), "+f"(c[2]), "+f"(c[3])
        : "r"(a[0]), "r"(a[1]), "r"(a[2]), "r"(a[3]), "r"(b[0]), "r"(b[1]));
}

// ---- init ----
__global__ void init_kernel() {
    const int i = blockIdx.x * 256 + threadIdx.x;
    if (i < BB * UU) {
        g_sbf[0][0][i] = __ushort_as_bfloat16(0);
        g_sbf[0][1][i] = __ushort_as_bfloat16(0);
    }
    if (i < 8 * 16 * 32) ((unsigned*)g_flags)[i] = 0u;
}

// ---- prep: transpose + hi/lo split of K and R ----
__global__ void prep_kernel(const float* __restrict__ Kw, const float* __restrict__ Rm) {
    const int gb = blockIdx.x;
    const int i = (gb & 1023) * 256 + threadIdx.x;
    const int n = i >> 9, k = i & 511;
    if (gb < 1024) {
        const float v = __ldg(&Kw[(size_t)k * UU + n]);
        const __nv_bfloat16 h = __float2bfloat16(v);
        g_Bh[i] = h;
        g_Bl[i] = __float2bfloat16(v - __bfloat162float(h));
    } else {
        const float v = __ldg(&Rm[(size_t)k * UU + n]);
        const __nv_bfloat16 h = __float2bfloat16(v);
        g_Rth[i] = h;
        g_Rtl[i] = __float2bfloat16(v - __bfloat162float(h));
    }
}

// ---- 1) conv, emits syn as bf16 hi/lo ----
__global__ void conv_kernel(const float* __restrict__ x, const float* __restrict__ pw,
                            const float* __restrict__ pb) {
    const int t = blockIdx.x, b = blockIdx.y, w4 = threadIdx.x;
    const float bias = pb[0];
    float4 acc = make_float4(bias, bias, bias, bias);
    const float4* xp = reinterpret_cast<const float4*>(x) + ((size_t)b * TT + t) * (WW / 4) + w4;
#pragma unroll
    for (int k = 0; k < PP; k++) {
        const float c = __ldg(&pw[k]);
        const float4 xv = xp[(size_t)k * (WW / 4)];
        acc.x += c * xv.x; acc.y += c * xv.y; acc.z += c * xv.z; acc.w += c * xv.w;
    }
    const float vv[4] = {acc.x, acc.y, acc.z, acc.w};
    uint32_t hw[2] = {0, 0}, lw[2] = {0, 0};
#pragma unroll
    for (int j = 0; j < 4; j++) {
        const __nv_bfloat16 h = __float2bfloat16(vv[j]);
        const __nv_bfloat16 l = __float2bfloat16(vv[j] - __bfloat162float(h));
        hw[j >> 1] |= (uint32_t)__bfloat16_as_ushort(h) << ((j & 1) * 16);
        lw[j >> 1] |= (uint32_t)__bfloat16_as_ushort(l) << ((j & 1) * 16);
    }
    const size_t idx = ((size_t)b * TP + t) * WW + w4 * 4;
    *(uint2*)&g_Ah[idx] = make_uint2(hw[0], hw[1]);
    *(uint2*)&g_Al[idx] = make_uint2(lw[0], lw[1]);
}

// ---- 2) pre = syn @ K + bias, bf16x3 mma.sync (unchanged from R6) ----
#define GEMM_SMEM 131072
__global__ __launch_bounds__(256, 1) void gemm_mma_kernel(const float* __restrict__ bias,
                                                          float* __restrict__ C) {
    extern __shared__ __align__(1024) char smem[];
    const uint32_t sb = smem_u32(smem);
    const int tid = threadIdx.x, lane = tid & 31, wid = tid >> 5;
    const int warp_m = wid & 3, warp_n = wid >> 2;
    const size_t m0 = (size_t)blockIdx.y * 128;
    const int n0 = blockIdx.x * 128;

    float acc[2][8][4];
#pragma unroll
    for (int i = 0; i < 2; i++)
#pragma unroll
        for (int j = 0; j < 8; j++)
#pragma unroll
            for (int q = 0; q < 4; q++) acc[i][j][q] = 0.0f;

    const int lcol = tid & 7, lrow = tid >> 3;
    auto load_stage = [&](int st, int k0) {
        const uint32_t sst = sb + st * 65536;
#pragma unroll
        for (int buf = 0; buf < 4; buf++) {
            const __nv_bfloat16* src = (buf == 0) ? g_Ah : (buf == 1) ? g_Al
                                     : (buf == 2) ? g_Bh : g_Bl;
            const size_t rbase = (buf < 2) ? m0 : (size_t)n0;
            const uint32_t sbuf = sst + buf * 16384;
#pragma unroll
            for (int i = 0; i < 4; i++) {
                const int row = lrow + 32 * i;
                cpa16(sbuf + SWZ((uint32_t)(row * 128 + lcol * 16)),
                      src + (rbase + row) * 512 + k0 + lcol * 8);
            }
        }
    };

    load_stage(0, 0);
    asm volatile("cp.async.commit_group;" ::: "memory");

    const int rsel = lane >> 3, rlow = lane & 7;
    const int radd = (rsel & 1) << 3, cadd = rsel >> 1;

    for (int c = 0; c < 8; c++) {
        if (c < 7) {
            load_stage((c + 1) & 1, (c + 1) << 6);
            asm volatile("cp.async.commit_group;" ::: "memory");
            asm volatile("cp.async.wait_group 1;" ::: "memory");
        } else {
            asm volatile("cp.async.wait_group 0;" ::: "memory");
        }
        __syncthreads();

        const uint32_t ss = sb + (c & 1) * 65536;
#pragma unroll
        for (int ks = 0; ks < 4; ks++) {
            uint32_t a[2][2][4];
#pragma unroll
            for (int h = 0; h < 2; h++)
#pragma unroll
                for (int mf = 0; mf < 2; mf++) {
                    const int row = warp_m * 32 + mf * 16 + radd + rlow;
                    const int col = ks * 2 + cadd;
                    const uint32_t ad = ss + h * 16384 + SWZ((uint32_t)(row * 128 + col * 16));
                    LDSM4(a[h][mf][0], a[h][mf][1], a[h][mf][2], a[h][mf][3], ad);
                }
            uint32_t b[2][8][2];
#pragma unroll
            for (int h = 0; h < 2; h++)
#pragma unroll
                for (int pr = 0; pr < 4; pr++) {
                    const int row = warp_n * 64 + pr * 16 + radd + rlow;
                    const int col = ks * 2 + cadd;
                    const uint32_t ad = ss + 32768 + h * 16384 +
                                        SWZ((uint32_t)(row * 128 + col * 16));
                    uint32_t r0, r1, r2, r3;
                    LDSM4(r0, r1, r2, r3, ad);
                    b[h][pr * 2][0] = r0; b[h][pr * 2 + 1][0] = r1;
                    b[h][pr * 2][1] = r2; b[h][pr * 2 + 1][1] = r3;
                }
#pragma unroll
            for (int mf = 0; mf < 2; mf++)
#pragma unroll
                for (int nf = 0; nf < 8; nf++) {
                    mma_bf16(acc[mf][nf], a[0][mf], b[0][nf]);
                    mma_bf16(acc[mf][nf], a[0][mf], b[1][nf]);
                    mma_bf16(acc[mf][nf], a[1][mf], b[0][nf]);
                }
        }
        __syncthreads();
    }

#pragma unroll
    for (int mf = 0; mf < 2; mf++) {
        const int row = warp_m * 32 + mf * 16 + (lane >> 2);
        const size_t gr0 = (m0 + row) * 512;
        const size_t gr1 = (m0 + row + 8) * 512;
#pragma unroll
        for (int nf = 0; nf < 8; nf++) {
            const int col = n0 + warp_n * 64 + nf * 8 + (lane & 3) * 2;
            const float2 bv = *(const float2*)&bias[col];
            *(float2*)&C[gr0 + col] =
                make_float2(acc[mf][nf][0] + bv.x, acc[mf][nf][1] + bv.y);
            *(float2*)&C[gr1 + col] =
                make_float2(acc[mf][nf][2] + bv.x, acc[mf][nf][3] + bv.y);
        }
    }
}

// ---- 3) persistent recurrence with tensor cores ----
// 128 CTAs = 8 bt x 16 ut. Tile 32b x 32u, K=512 split 8 warps x 64k.
// R^T hi/lo fragments live in registers for the whole sequence.
// SMEM: state hi [0,32K) lo [32K,64K) chunked [chunk][row][128B]; buf [64K,96K).
#define RNN_SMEM 98304
__global__ __launch_bounds__(256, 1) void rnn_tc_kernel(float* __restrict__ C) {
    extern __shared__ __align__(1024) char smem[];
    const uint32_t sb = smem_u32(smem);
    float* buf = (float*)(smem + 65536);

    const int tid = threadIdx.x, lane = tid & 31, wid = tid >> 5;
    const int ut = blockIdx.x, bt = blockIdx.y;
    const int n0 = ut << 5, b0 = bt << 5;

    const int rsel = lane >> 3, rlow = lane & 7;
    const int radd = (rsel & 1) << 3, cadd = rsel >> 1;
    const uint32_t chunk_base = sb + (uint32_t)(wid << 12);

    // ---- stage R^T tile [32 n][512 k] hi/lo into SMEM, then to registers ----
#pragma unroll
    for (int i = 0; i < 8; i++) {
        const int unit = tid + (i << 8);
        const int chunk = unit >> 8, rem = unit & 255;
        const int row = rem >> 3, col = rem & 7;
        const uint32_t soff = (uint32_t)(chunk << 12) + SWZ((uint32_t)(row * 128 + col * 16));
        const size_t gidx = (size_t)(n0 + row) * 512 + chunk * 64 + col * 8;
        cpa16(sb + soff, g_Rth + gidx);
        cpa16(sb + 32768 + soff, g_Rtl + gidx);
    }
    asm volatile("cp.async.commit_group;" ::: "memory");
    asm volatile("cp.async.wait_group 0;" ::: "memory");
    __syncthreads();

    uint32_t bfr[2][4][4][2];   // [hi/lo][n8][k16][reg]
#pragma unroll
    for (int h = 0; h < 2; h++)
#pragma unroll
        for (int pr = 0; pr < 2; pr++)
#pragma unroll
            for (int ks = 0; ks < 4; ks++) {
                const int row = pr * 16 + radd + rlow;
                const int col = ks * 2 + cadd;
                const uint32_t ad = chunk_base + h * 32768 +
                                    SWZ((uint32_t)(row * 128 + col * 16));
                uint32_t r0, r1, r2, r3;
                LDSM4(r0, r1, r2, r3, ad);
                bfr[h][pr * 2][ks][0] = r0; bfr[h][pr * 2 + 1][ks][0] = r1;
                bfr[h][pr * 2][ks][1] = r2; bfr[h][pr * 2 + 1][ks][1] = r3;
            }
    __syncthreads();

    // epilogue ownership: 4 consecutive u per thread
    const int e_b = tid >> 3;                 // 0..31
    const int e_u = (tid & 7) << 2;           // 0..28
    const int bglob = b0 + e_b;
    const size_t srow = (size_t)bglob * UU + n0 + e_u;

    for (int t = 0; t < TP; t++) {
        const int p = t & 1;
        if (t > 0 && tid < 16) {
            const unsigned* fp = &g_flags[bt][tid * 32];
            while (ld_acq(fp) < (unsigned)t) {}
        }
        __syncthreads();

        // load state tile 32b x 512k hi/lo
        const __nv_bfloat16* sh_g = g_sbf[p][0];
        const __nv_bfloat16* sl_g = g_sbf[p][1];
#pragma unroll
        for (int i = 0; i < 8; i++) {
            const int unit = tid + (i << 8);
            const int chunk = unit >> 8, rem = unit & 255;
            const int row = rem >> 3, col = rem & 7;
            const uint32_t soff = (uint32_t)(chunk << 12) +
                                  SWZ((uint32_t)(row * 128 + col * 16));
            const size_t gidx = (size_t)(b0 + row) * 512 + chunk * 64 + col * 8;
            cpa16(sb + soff, sh_g + gidx);
            cpa16(sb + 32768 + soff, sl_g + gidx);
        }
        asm volatile("cp.async.commit_group;" ::: "memory");
        asm volatile("cp.async.wait_group 0;" ::: "memory");
        __syncthreads();

        float acc[2][4][4];
#pragma unroll
        for (int mf = 0; mf < 2; mf++)
#pragma unroll
            for (int nf = 0; nf < 4; nf++)
#pragma unroll
                for (int q = 0; q < 4; q++) acc[mf][nf][q] = 0.0f;

#pragma unroll
        for (int ks = 0; ks < 4; ks++) {
            uint32_t ah[2][4], al[2][4];
#pragma unroll
            for (int mf = 0; mf < 2; mf++) {
                const int row = mf * 16 + radd + rlow;
                const int col = ks * 2 + cadd;
                const uint32_t off = SWZ((uint32_t)(row * 128 + col * 16));
                LDSM4(ah[mf][0], ah[mf][1], ah[mf][2], ah[mf][3], chunk_base + off);
                LDSM4(al[mf][0], al[mf][1], al[mf][2], al[mf][3], chunk_base + 32768 + off);
            }
#pragma unroll
            for (int mf = 0; mf < 2; mf++)
#pragma unroll
                for (int nf = 0; nf < 4; nf++) {
                    mma_bf16(acc[mf][nf], ah[mf], bfr[0][nf][ks]);
                    mma_bf16(acc[mf][nf], ah[mf], bfr[1][nf][ks]);
                    mma_bf16(acc[mf][nf], al[mf], bfr[0][nf][ks]);
                }
        }
        __syncthreads();   // everyone done with state SMEM? (buf is separate; sync for partials)

        // stash partials: buf[wid][m32][n32]
#pragma unroll
        for (int mf = 0; mf < 2; mf++)
#pragma unroll
            for (int nf = 0; nf < 4; nf++) {
                const int row = mf * 16 + (lane >> 2);
                const int col = nf * 8 + ((lane & 3) << 1);
                float* bp = buf + (wid << 10) + row * 32 + col;
                bp[0] = acc[mf][nf][0]; bp[1] = acc[mf][nf][1];
                bp[256] = acc[mf][nf][2]; bp[257] = acc[mf][nf][3];  // row+8
            }
        __syncthreads();

        // reduce 8 warps, 4 outputs per thread
        const float4* b4 = (const float4*)buf;
        float4 s = b4[tid];
#pragma unroll
        for (int w = 1; w < 8; w++) {
            const float4 v = b4[(w << 8) + tid];
            s.x += v.x; s.y += v.y; s.z += v.z; s.w += v.w;
        }

        const size_t crow = ((size_t)bglob * TP + t) * UU + n0 + e_u;
        const float4 pre = *(const float4*)&C[crow];
        const float o[4] = {pre.x + s.x, pre.y + s.y, pre.z + s.z, pre.w + s.w};
        float nn[4];
        uint32_t hw[2] = {0, 0}, lw[2] = {0, 0};
#pragma unroll
        for (int j = 0; j < 4; j++) {
            const float n = 1.0f / (1.0f + __expf(-3.0f * o[j]));
            nn[j] = n;
            const float st = o[j] / (1.0f + __expf(2.0f * n - 1.0f));
            const __nv_bfloat16 h = __float2bfloat16(st);
            const __nv_bfloat16 l = __float2bfloat16(st - __bfloat162float(h));
            hw[j >> 1] |= (uint32_t)__bfloat16_as_ushort(h) << ((j & 1) * 16);
            lw[j >> 1] |= (uint32_t)__bfloat16_as_ushort(l) << ((j & 1) * 16);
        }
        // state first (critical path), then flags, then output
        *(uint2*)&g_sbf[p ^ 1][0][srow] = make_uint2(hw[0], hw[1]);
        *(uint2*)&g_sbf[p ^ 1][1][srow] = make_uint2(lw[0], lw[1]);
        __threadfence();
        __syncthreads();
        if (tid == 0) st_rel(&g_flags[bt][ut * 32], (unsigned)(t + 1));

        *(float4*)&C[crow] = make_float4(nn[0], nn[1], nn[2], nn[3]);
    }
}

extern "C" void kernel_launch(void* const* d_in, const int* in_sizes, int n_in,
                              void* d_out, int out_size) {
    const float* x    = (const float*)d_in[0];
    const float* pw   = (const float*)d_in[1];
    const float* pb   = (const float*)d_in[2];
    const float* Kw   = (const float*)d_in[3];
    const float* Rm   = (const float*)d_in[4];
    const float* bias = (const float*)d_in[5];
    float* out = (float*)d_out;

    cudaFuncSetAttribute(gemm_mma_kernel,
                         cudaFuncAttributeMaxDynamicSharedMemorySize, GEMM_SMEM);
    cudaFuncSetAttribute(rnn_tc_kernel,
                         cudaFuncAttributeMaxDynamicSharedMemorySize, RNN_SMEM);

    init_kernel<<<(BB * UU) / 256, 256>>>();
    prep_kernel<<<2048, 256>>>(Kw, Rm);
    conv_kernel<<<dim3(TP, BB), 128>>>(x, pw, pb);
    gemm_mma_kernel<<<dim3(UU / 128, MTOT / 128), 256, GEMM_SMEM>>>(bias, out);
    rnn_tc_kernel<<<dim3(16, 8), 256, RNN_SMEM>>>(out);
}